// round 1
// baseline (speedup 1.0000x reference)
#include <cuda_runtime.h>

#define NN 100000
#define DD 128
#define EMAX 1600000

// ---------------- scratch (device globals: no allocation allowed) ----------------
__device__ float g_K[NN * DD];
__device__ float g_QV[NN * 2 * DD];   // per node: q[0..127], v[128..255]
__device__ float g_S[NN * DD];
__device__ float g_H1[NN * DD];
__device__ float g_H2[NN * DD];
__device__ float4 g_P3[NN];           // layer3: (k, q, v, s+b)
__device__ int g_counts[NN];
__device__ int g_rowoff[NN + 1];
__device__ int g_cursor[NN];
__device__ int g_srcsorted[EMAX];

// ---------------- FMA-only fast sigmoid (no MUFU) ----------------
// sigmoid(t) = 1 / (1 + 2^(-t*log2(e)))
__device__ __forceinline__ float fsig(float t) {
    float u = t * -1.4426950408889634f;          // log2(e^-t)
    u = fminf(fmaxf(u, -24.0f), 24.0f);
    float z = __fadd_rn(u, 12582912.0f);         // round-to-nearest-int trick (2^23*1.5)
    int n = __float_as_int(z) - 0x4B400000;      // integer part
    float f = __fsub_rn(u, __fsub_rn(z, 12582912.0f));  // frac in [-0.5, 0.5]
    // 2^f, degree-6 Taylor in ln2 (abs err ~1e-7 on [-0.5,0.5])
    float p = 1.5403530e-4f;
    p = fmaf(p, f, 1.3333558e-3f);
    p = fmaf(p, f, 9.6181291e-3f);
    p = fmaf(p, f, 5.5504109e-2f);
    p = fmaf(p, f, 2.4022651e-1f);
    p = fmaf(p, f, 6.9314718e-1f);
    p = fmaf(p, f, 1.0f);
    float e = __int_as_float(__float_as_int(p) + (n << 23));   // 2^(n+f)
    float d = 1.0f + e;
    // bit-trick reciprocal + 3 Newton iterations (rel err < 1e-9)
    float r = __int_as_float(0x7EF311C3 - __float_as_int(d));
    r = r * fmaf(-d, r, 2.0f);
    r = r * fmaf(-d, r, 2.0f);
    r = r * fmaf(-d, r, 2.0f);
    return r;
}

// ---------------- CSR build ----------------
__global__ void zero_counts_k(int n) {
    int i = blockIdx.x * blockDim.x + threadIdx.x;
    if (i < n) g_counts[i] = 0;
}

__global__ void hist_k(const int* __restrict__ dst, int e) {
    int i = blockIdx.x * blockDim.x + threadIdx.x;
    if (i < e) atomicAdd(&g_counts[dst[i]], 1);
}

__global__ void scan_k(int n) {
    __shared__ int sums[1024];
    int tid = threadIdx.x;
    int chunk = (n + 1023) >> 10;
    int b = tid * chunk, e = min(b + chunk, n);
    int s = 0;
    for (int i = b; i < e; i++) s += g_counts[i];
    sums[tid] = s;
    __syncthreads();
    for (int off = 1; off < 1024; off <<= 1) {
        int v = (tid >= off) ? sums[tid - off] : 0;
        __syncthreads();
        sums[tid] += v;
        __syncthreads();
    }
    int run = tid ? sums[tid - 1] : 0;
    for (int i = b; i < e; i++) {
        g_rowoff[i] = run;
        g_cursor[i] = run;
        run += g_counts[i];
    }
    if (tid == 1023) g_rowoff[n] = sums[1023];
}

__global__ void scatter_k(const int* __restrict__ src, const int* __restrict__ dst, int e) {
    int i = blockIdx.x * blockDim.x + threadIdx.x;
    if (i < e) {
        int p = atomicAdd(&g_cursor[dst[i]], 1);
        g_srcsorted[p] = src[i];
    }
}

// ---------------- fp32 SGEMM: out[n,128] = X[n,128] @ W[128,128] (+bias) ----------------
// BM=128, BN=128, BK=16, 256 threads, 8x8 microtile per thread
__global__ void __launch_bounds__(256) gemm128(
    const float* __restrict__ X, const float* __restrict__ W,
    const float* __restrict__ bias, float* __restrict__ out,
    int ostride, int nrows)
{
    __shared__ float As[16][132];   // [k][m], stride mult of 4 -> float4-aligned rows
    __shared__ float Bs[16][132];   // [k][n]
    int tid = threadIdx.x;
    int tx = tid & 15, ty = tid >> 4;
    int row0 = blockIdx.x * 128;

    float acc[8][8];
#pragma unroll
    for (int i = 0; i < 8; i++)
#pragma unroll
        for (int j = 0; j < 8; j++) acc[i][j] = 0.0f;

    int ar = tid & 127;             // conflict-free transposed A stores
    int ac = (tid >> 7) << 3;       // 0 or 8
    int gr = row0 + ar;
    const float* xrow = X + (size_t)gr * DD;

    for (int k0 = 0; k0 < DD; k0 += 16) {
        float4 a0 = make_float4(0.f, 0.f, 0.f, 0.f), a1 = a0;
        if (gr < nrows) {
            a0 = *(const float4*)(xrow + k0 + ac);
            a1 = *(const float4*)(xrow + k0 + ac + 4);
        }
        As[ac + 0][ar] = a0.x; As[ac + 1][ar] = a0.y; As[ac + 2][ar] = a0.z; As[ac + 3][ar] = a0.w;
        As[ac + 4][ar] = a1.x; As[ac + 5][ar] = a1.y; As[ac + 6][ar] = a1.z; As[ac + 7][ar] = a1.w;
        float4 b0 = *(const float4*)(W + (size_t)(k0 + ty) * DD + tx * 8);
        float4 b1 = *(const float4*)(W + (size_t)(k0 + ty) * DD + tx * 8 + 4);
        *(float4*)&Bs[ty][tx * 8] = b0;
        *(float4*)&Bs[ty][tx * 8 + 4] = b1;
        __syncthreads();
#pragma unroll
        for (int kk = 0; kk < 16; kk++) {
            float4 a0r = *(const float4*)&As[kk][ty * 8];
            float4 a1r = *(const float4*)&As[kk][ty * 8 + 4];
            float4 b0r = *(const float4*)&Bs[kk][tx * 8];
            float4 b1r = *(const float4*)&Bs[kk][tx * 8 + 4];
            float a[8] = {a0r.x, a0r.y, a0r.z, a0r.w, a1r.x, a1r.y, a1r.z, a1r.w};
            float b[8] = {b0r.x, b0r.y, b0r.z, b0r.w, b1r.x, b1r.y, b1r.z, b1r.w};
#pragma unroll
            for (int i = 0; i < 8; i++)
#pragma unroll
                for (int j = 0; j < 8; j++)
                    acc[i][j] = fmaf(a[i], b[j], acc[i][j]);
        }
        __syncthreads();
    }

    float bv[8];
#pragma unroll
    for (int j = 0; j < 8; j++) bv[j] = bias ? bias[tx * 8 + j] : 0.0f;

#pragma unroll
    for (int i = 0; i < 8; i++) {
        int r = row0 + ty * 8 + i;
        if (r < nrows) {
            float* orow = out + (size_t)r * ostride + tx * 8;
            float4 v0 = make_float4(acc[i][0] + bv[0], acc[i][1] + bv[1],
                                    acc[i][2] + bv[2], acc[i][3] + bv[3]);
            float4 v1 = make_float4(acc[i][4] + bv[4], acc[i][5] + bv[5],
                                    acc[i][6] + bv[6], acc[i][7] + bv[7]);
            *(float4*)(orow) = v0;
            *(float4*)(orow + 4) = v1;
        }
    }
}

// ---------------- gated aggregation, D=128: warp per node ----------------
__global__ void __launch_bounds__(256) agg128(float* __restrict__ out, int relu, int n) {
    int node = blockIdx.x * 8 + (threadIdx.x >> 5);
    if (node >= n) return;
    int lane = threadIdx.x & 31;
    int beg = g_rowoff[node], end = g_rowoff[node + 1];
    const float4* kp = (const float4*)(g_K + (size_t)node * DD);
    float4 k = kp[lane];
    float4 acc = make_float4(0.f, 0.f, 0.f, 0.f);
    const float4* QV4 = (const float4*)g_QV;
    for (int e = beg; e < end; e++) {
        int s = g_srcsorted[e];
        const float4* qv = QV4 + (size_t)s * 64;
        float4 q = __ldg(&qv[lane]);
        float4 v = __ldg(&qv[32 + lane]);
        acc.x = fmaf(fsig(k.x + q.x), v.x, acc.x);
        acc.y = fmaf(fsig(k.y + q.y), v.y, acc.y);
        acc.z = fmaf(fsig(k.z + q.z), v.z, acc.z);
        acc.w = fmaf(fsig(k.w + q.w), v.w, acc.w);
    }
    const float4* sp = (const float4*)(g_S + (size_t)node * DD);
    float4 sv = sp[lane];
    float4 r = make_float4(acc.x + sv.x, acc.y + sv.y, acc.z + sv.z, acc.w + sv.w);
    if (relu) {
        r.x = fmaxf(r.x, 0.f); r.y = fmaxf(r.y, 0.f);
        r.z = fmaxf(r.z, 0.f); r.w = fmaxf(r.w, 0.f);
    }
    ((float4*)(out + (size_t)node * DD))[lane] = r;
}

// ---------------- layer 3 projection: 4 dot products per node (Dout=1) ----------------
__global__ void __launch_bounds__(256) proj3_k(
    const float* __restrict__ Wk, const float* __restrict__ Wq,
    const float* __restrict__ Wv, const float* __restrict__ Ws,
    const float* __restrict__ b, int n)
{
    __shared__ float w[4][128];
    int tid = threadIdx.x;
    if (tid < 128) { w[0][tid] = Wk[tid]; w[1][tid] = Wq[tid]; }
    else { int t = tid - 128; w[2][t] = Wv[t]; w[3][t] = Ws[t]; }
    __syncthreads();
    int node = blockIdx.x * 8 + (tid >> 5);
    if (node >= n) return;
    int lane = tid & 31;
    float4 h = ((const float4*)(g_H2 + (size_t)node * DD))[lane];
    int c = lane * 4;
    float pk = h.x * w[0][c] + h.y * w[0][c + 1] + h.z * w[0][c + 2] + h.w * w[0][c + 3];
    float pq = h.x * w[1][c] + h.y * w[1][c + 1] + h.z * w[1][c + 2] + h.w * w[1][c + 3];
    float pv = h.x * w[2][c] + h.y * w[2][c + 1] + h.z * w[2][c + 2] + h.w * w[2][c + 3];
    float ps = h.x * w[3][c] + h.y * w[3][c + 1] + h.z * w[3][c + 2] + h.w * w[3][c + 3];
#pragma unroll
    for (int o = 16; o; o >>= 1) {
        pk += __shfl_xor_sync(0xFFFFFFFFu, pk, o);
        pq += __shfl_xor_sync(0xFFFFFFFFu, pq, o);
        pv += __shfl_xor_sync(0xFFFFFFFFu, pv, o);
        ps += __shfl_xor_sync(0xFFFFFFFFu, ps, o);
    }
    if (lane == 0) g_P3[node] = make_float4(pk, pq, pv, ps + b[0]);
}

// ---------------- layer 3 aggregation: thread per node ----------------
__global__ void agg3_k(float* __restrict__ out, int n) {
    int i = blockIdx.x * blockDim.x + threadIdx.x;
    if (i >= n) return;
    float4 p = g_P3[i];
    float acc = p.w;   // s + b
    int beg = g_rowoff[i], end = g_rowoff[i + 1];
    for (int e = beg; e < end; e++) {
        float4 ps = __ldg(&g_P3[g_srcsorted[e]]);
        acc = fmaf(fsig(p.x + ps.y), ps.z, acc);
    }
    out[i] = acc;
}

// ---------------- launch ----------------
extern "C" void kernel_launch(void* const* d_in, const int* in_sizes, int n_in,
                              void* d_out, int out_size) {
    const float* x  = (const float*)d_in[0];
    const int*   ei = (const int*)d_in[1];
    const float* Wk1 = (const float*)d_in[2];
    const float* Wq1 = (const float*)d_in[3];
    const float* Wv1 = (const float*)d_in[4];
    const float* Ws1 = (const float*)d_in[5];
    const float* b1  = (const float*)d_in[6];
    const float* Wk2 = (const float*)d_in[7];
    const float* Wq2 = (const float*)d_in[8];
    const float* Wv2 = (const float*)d_in[9];
    const float* Ws2 = (const float*)d_in[10];
    const float* b2  = (const float*)d_in[11];
    const float* Wk3 = (const float*)d_in[12];
    const float* Wq3 = (const float*)d_in[13];
    const float* Wv3 = (const float*)d_in[14];
    const float* Ws3 = (const float*)d_in[15];
    const float* b3  = (const float*)d_in[16];

    int N = in_sizes[0] / DD;     // 100000
    int E = in_sizes[1] / 2;      // 1600000
    const int* src = ei;
    const int* dst = ei + E;

    void *pK, *pQV, *pS, *pH1, *pH2;
    cudaGetSymbolAddress(&pK, g_K);
    cudaGetSymbolAddress(&pQV, g_QV);
    cudaGetSymbolAddress(&pS, g_S);
    cudaGetSymbolAddress(&pH1, g_H1);
    cudaGetSymbolAddress(&pH2, g_H2);
    float* K  = (float*)pK;
    float* QV = (float*)pQV;
    float* S  = (float*)pS;
    float* H1 = (float*)pH1;
    float* H2 = (float*)pH2;

    // CSR by dst
    zero_counts_k<<<(N + 255) / 256, 256>>>(N);
    hist_k<<<(E + 255) / 256, 256>>>(dst, E);
    scan_k<<<1, 1024>>>(N);
    scatter_k<<<(E + 255) / 256, 256>>>(src, dst, E);

    int gb = (N + 127) / 128;
    int ab = (N + 7) / 8;

    // layer 1
    gemm128<<<gb, 256>>>(x, Wk1, nullptr, K, DD, N);
    gemm128<<<gb, 256>>>(x, Wq1, nullptr, QV, 2 * DD, N);
    gemm128<<<gb, 256>>>(x, Wv1, nullptr, QV + DD, 2 * DD, N);
    gemm128<<<gb, 256>>>(x, Ws1, b1, S, DD, N);
    agg128<<<ab, 256>>>(H1, 1, N);

    // layer 2
    gemm128<<<gb, 256>>>(H1, Wk2, nullptr, K, DD, N);
    gemm128<<<gb, 256>>>(H1, Wq2, nullptr, QV, 2 * DD, N);
    gemm128<<<gb, 256>>>(H1, Wv2, nullptr, QV + DD, 2 * DD, N);
    gemm128<<<gb, 256>>>(H1, Ws2, b2, S, DD, N);
    agg128<<<ab, 256>>>(H2, 1, N);

    // layer 3
    proj3_k<<<ab, 256>>>(Wk3, Wq3, Wv3, Ws3, b3, N);
    agg3_k<<<(N + 255) / 256, 256>>>((float*)d_out, N);
}

// round 3
// speedup vs baseline: 1.6043x; 1.6043x over previous
#include <cuda_runtime.h>
#include <cuda_bf16.h>
#include <cstdint>

#define NN 100000
#define DD 128
#define EMAX 1600000
#define NP 100096          // 782 * 128 (padded rows)
#define NBLK 782
#define TSTRIDE 136        // padded bf16 row stride: conflict-free ldmatrix

// ---------------- scratch (device globals: no allocation allowed) ----------------
__device__ float g_K[NP * DD];
__device__ float g_QV[NP * 2 * DD];   // per node: q[0..127], v[128..255]
__device__ float g_S[NP * DD];
__device__ float g_H1[NP * DD];
__device__ float g_H2[NP * DD];
__device__ __nv_bfloat16 g_Ahi[NP * DD];
__device__ __nv_bfloat16 g_Alo[NP * DD];
__device__ __nv_bfloat16 g_Whi[512 * 128];   // [n_out][k], n_out = concat(k,q,v,s)
__device__ __nv_bfloat16 g_Wlo[512 * 128];
__device__ float4 g_P3[NP];
__device__ int g_counts[NN];
__device__ int g_rowoff[NN + 1];
__device__ int g_cursor[NN];
__device__ int g_srcsorted[EMAX];

// ---------------- helpers ----------------
__device__ __forceinline__ uint32_t smem_u32(const void* p) {
    uint32_t a;
    asm("{ .reg .u64 t; cvta.to.shared.u64 t, %1; cvt.u32.u64 %0, t; }" : "=r"(a) : "l"(p));
    return a;
}

#define LDSM_X4(r0, r1, r2, r3, addr)                                          \
    asm volatile("ldmatrix.sync.aligned.m8n8.x4.shared.b16 {%0,%1,%2,%3}, [%4];" \
                 : "=r"(r0), "=r"(r1), "=r"(r2), "=r"(r3) : "r"(addr))

#define MMA16816(d, a, b0, b1)                                                 \
    asm volatile("mma.sync.aligned.m16n8k16.row.col.f32.bf16.bf16.f32 "        \
                 "{%0,%1,%2,%3}, {%4,%5,%6,%7}, {%8,%9}, {%0,%1,%2,%3};"       \
                 : "+f"((d)[0]), "+f"((d)[1]), "+f"((d)[2]), "+f"((d)[3])      \
                 : "r"((a)[0]), "r"((a)[1]), "r"((a)[2]), "r"((a)[3]),         \
                   "r"(b0), "r"(b1))

// ---------------- MUFU-based sigmoid ----------------
__device__ __forceinline__ float fsig(float t) {
    return __fdividef(1.0f, 1.0f + __expf(-t));
}

// ---------------- CSR build ----------------
__global__ void zero_counts_k(int n) {
    int i = blockIdx.x * blockDim.x + threadIdx.x;
    if (i < n) g_counts[i] = 0;
}
__global__ void hist_k(const int* __restrict__ dst, int e) {
    int i = blockIdx.x * blockDim.x + threadIdx.x;
    if (i < e) atomicAdd(&g_counts[dst[i]], 1);
}
__global__ void scan_k(int n) {
    __shared__ int sums[1024];
    int tid = threadIdx.x;
    int chunk = (n + 1023) >> 10;
    int b = tid * chunk, e = min(b + chunk, n);
    int s = 0;
    for (int i = b; i < e; i++) s += g_counts[i];
    sums[tid] = s;
    __syncthreads();
    for (int off = 1; off < 1024; off <<= 1) {
        int v = (tid >= off) ? sums[tid - off] : 0;
        __syncthreads();
        sums[tid] += v;
        __syncthreads();
    }
    int run = tid ? sums[tid - 1] : 0;
    for (int i = b; i < e; i++) {
        g_rowoff[i] = run;
        g_cursor[i] = run;
        run += g_counts[i];
    }
    if (tid == 1023) g_rowoff[n] = sums[1023];
}
__global__ void scatter_k(const int* __restrict__ src, const int* __restrict__ dst, int e) {
    int i = blockIdx.x * blockDim.x + threadIdx.x;
    if (i < e) {
        int p = atomicAdd(&g_cursor[dst[i]], 1);
        g_srcsorted[p] = src[i];
    }
}

// ---------------- bf16 split conversion ----------------
__global__ void cvt_k(const float* __restrict__ x, int nreal) {
    int i = (blockIdx.x * blockDim.x + threadIdx.x) * 8;
    if (i >= NP * DD) return;
    __nv_bfloat16 h[8], l[8];
#pragma unroll
    for (int j = 0; j < 8; j++) {
        float v = (i + j < nreal) ? x[i + j] : 0.0f;
        h[j] = __float2bfloat16(v);
        l[j] = __float2bfloat16(v - __bfloat162float(h[j]));
    }
    *(uint4*)(g_Ahi + i) = *(uint4*)h;
    *(uint4*)(g_Alo + i) = *(uint4*)l;
}

__global__ void packw_k(const float* __restrict__ Wk, const float* __restrict__ Wq,
                        const float* __restrict__ Wv, const float* __restrict__ Ws) {
    int i = blockIdx.x * blockDim.x + threadIdx.x;   // 512*128
    if (i >= 512 * 128) return;
    int n = i >> 7, k = i & 127;
    const float* W = (n < 128) ? Wk : (n < 256) ? Wq : (n < 384) ? Wv : Ws;
    float v = W[k * 128 + (n & 127)];
    __nv_bfloat16 h = __float2bfloat16(v);
    g_Whi[i] = h;
    g_Wlo[i] = __float2bfloat16(v - __bfloat162float(h));
}

// ---------------- mma.sync bf16 split GEMM ----------------
// CTA: 128 rows x 128 cols (of N=512 concat), K=128 resident in SMEM.
// 256 threads = 8 warps (4 m-blocks x 2 n-blocks); warp tile 32x64.
// acc = Ahi*Bhi + Alo*Bhi + Ahi*Blo  (fp32 accum; rel err ~2^-17)
__global__ void __launch_bounds__(256, 1) mma_gemm(const float* __restrict__ bias) {
    extern __shared__ __nv_bfloat16 sm[];
    __nv_bfloat16* Ah = sm;
    __nv_bfloat16* Al = sm + 128 * TSTRIDE;
    __nv_bfloat16* Bh = sm + 2 * 128 * TSTRIDE;
    __nv_bfloat16* Bl = sm + 3 * 128 * TSTRIDE;

    int tid = threadIdx.x;
    int row0 = blockIdx.x * 128;
    int col0 = blockIdx.y * 128;

    // cooperative load: each thread 8 x uint4 per tile
#pragma unroll
    for (int i = 0; i < 8; i++) {
        int c = tid + i * 256;
        int r = c >> 4, col = (c & 15) * 8;
        *(uint4*)(Ah + r * TSTRIDE + col) = *(const uint4*)(g_Ahi + (size_t)(row0 + r) * 128 + col);
        *(uint4*)(Al + r * TSTRIDE + col) = *(const uint4*)(g_Alo + (size_t)(row0 + r) * 128 + col);
        *(uint4*)(Bh + r * TSTRIDE + col) = *(const uint4*)(g_Whi + (size_t)(col0 + r) * 128 + col);
        *(uint4*)(Bl + r * TSTRIDE + col) = *(const uint4*)(g_Wlo + (size_t)(col0 + r) * 128 + col);
    }
    __syncthreads();

    int w = tid >> 5, lane = tid & 31;
    int m_base = (w & 3) * 32;
    int n_base = (w >> 2) * 64;

    float acc[2][8][4];
#pragma unroll
    for (int mi = 0; mi < 2; mi++)
#pragma unroll
        for (int ni = 0; ni < 8; ni++)
#pragma unroll
            for (int j = 0; j < 4; j++) acc[mi][ni][j] = 0.0f;

    // ldmatrix address patterns
    int a_row = lane & 15, a_colsel = (lane >> 4) * 8;          // A x4: m16 x k16
    int b_grp = lane >> 3;                                      // B x4: n16 x k16
    int b_row = (b_grp >> 1) * 8 + (lane & 7);
    int b_col = (b_grp & 1) * 8;

    uint32_t sAh = smem_u32(Ah), sAl = smem_u32(Al);
    uint32_t sBh = smem_u32(Bh), sBl = smem_u32(Bl);

#pragma unroll
    for (int ks = 0; ks < 8; ks++) {
        int k0 = ks * 16;
        uint32_t ah[2][4], al[2][4], bh[4][4], bl[4][4];
#pragma unroll
        for (int mi = 0; mi < 2; mi++) {
            uint32_t off = (uint32_t)((m_base + mi * 16 + a_row) * TSTRIDE + k0 + a_colsel) * 2;
            LDSM_X4(ah[mi][0], ah[mi][1], ah[mi][2], ah[mi][3], sAh + off);
            LDSM_X4(al[mi][0], al[mi][1], al[mi][2], al[mi][3], sAl + off);
        }
#pragma unroll
        for (int j = 0; j < 4; j++) {
            uint32_t off = (uint32_t)((n_base + j * 16 + b_row) * TSTRIDE + k0 + b_col) * 2;
            LDSM_X4(bh[j][0], bh[j][1], bh[j][2], bh[j][3], sBh + off);
            LDSM_X4(bl[j][0], bl[j][1], bl[j][2], bl[j][3], sBl + off);
        }
#pragma unroll
        for (int mi = 0; mi < 2; mi++)
#pragma unroll
            for (int ni = 0; ni < 8; ni++) {
                int j = ni >> 1, h = (ni & 1) * 2;
                MMA16816(acc[mi][ni], ah[mi], bh[j][h], bh[j][h + 1]);
                MMA16816(acc[mi][ni], al[mi], bh[j][h], bh[j][h + 1]);
                MMA16816(acc[mi][ni], ah[mi], bl[j][h], bl[j][h + 1]);
            }
    }

    // epilogue: scatter into K / QV / S
    int by = blockIdx.y;
    float* base;
    int stride, coff;
    if (by == 0)      { base = g_K;  stride = 128; coff = 0; }
    else if (by == 1) { base = g_QV; stride = 256; coff = 0; }
    else if (by == 2) { base = g_QV; stride = 256; coff = 128; }
    else              { base = g_S;  stride = 128; coff = 0; }

    int r_in = lane >> 2;
    int c_in = (lane & 3) * 2;
#pragma unroll
    for (int mi = 0; mi < 2; mi++)
#pragma unroll
        for (int half = 0; half < 2; half++)
#pragma unroll
            for (int ni = 0; ni < 8; ni++) {
                int r = row0 + m_base + mi * 16 + half * 8 + r_in;
                int c = n_base + ni * 8 + c_in;
                float2 v = make_float2(acc[mi][ni][half * 2], acc[mi][ni][half * 2 + 1]);
                if (by == 3) {
                    v.x += __ldg(&bias[c]);
                    v.y += __ldg(&bias[c + 1]);
                }
                *(float2*)(base + (size_t)r * stride + coff + c) = v;
            }
}

// ---------------- gated aggregation, D=128: warp per node ----------------
__global__ void __launch_bounds__(256) agg128(float* __restrict__ out, int relu, int n) {
    int node = blockIdx.x * 8 + (threadIdx.x >> 5);
    if (node >= n) return;
    int lane = threadIdx.x & 31;
    int beg = g_rowoff[node], end = g_rowoff[node + 1];
    const float4* kp = (const float4*)(g_K + (size_t)node * DD);
    float4 k = kp[lane];
    float4 acc = make_float4(0.f, 0.f, 0.f, 0.f);
    const float4* QV4 = (const float4*)g_QV;
    for (int e = beg; e < end; e++) {
        int s = g_srcsorted[e];
        const float4* qv = QV4 + (size_t)s * 64;
        float4 q = __ldg(&qv[lane]);
        float4 v = __ldg(&qv[32 + lane]);
        acc.x = fmaf(fsig(k.x + q.x), v.x, acc.x);
        acc.y = fmaf(fsig(k.y + q.y), v.y, acc.y);
        acc.z = fmaf(fsig(k.z + q.z), v.z, acc.z);
        acc.w = fmaf(fsig(k.w + q.w), v.w, acc.w);
    }
    const float4* sp = (const float4*)(g_S + (size_t)node * DD);
    float4 sv = sp[lane];
    float4 r = make_float4(acc.x + sv.x, acc.y + sv.y, acc.z + sv.z, acc.w + sv.w);
    if (relu) {
        r.x = fmaxf(r.x, 0.f); r.y = fmaxf(r.y, 0.f);
        r.z = fmaxf(r.z, 0.f); r.w = fmaxf(r.w, 0.f);
    }
    ((float4*)(out + (size_t)node * DD))[lane] = r;
}

// ---------------- layer 3 projection: 4 dot products per node (Dout=1) ----------------
__global__ void __launch_bounds__(256) proj3_k(
    const float* __restrict__ Wk, const float* __restrict__ Wq,
    const float* __restrict__ Wv, const float* __restrict__ Ws,
    const float* __restrict__ b, int n)
{
    __shared__ float w[4][128];
    int tid = threadIdx.x;
    if (tid < 128) { w[0][tid] = Wk[tid]; w[1][tid] = Wq[tid]; }
    else { int t = tid - 128; w[2][t] = Wv[t]; w[3][t] = Ws[t]; }
    __syncthreads();
    int node = blockIdx.x * 8 + (tid >> 5);
    if (node >= n) return;
    int lane = tid & 31;
    float4 h = ((const float4*)(g_H2 + (size_t)node * DD))[lane];
    int c = lane * 4;
    float pk = h.x * w[0][c] + h.y * w[0][c + 1] + h.z * w[0][c + 2] + h.w * w[0][c + 3];
    float pq = h.x * w[1][c] + h.y * w[1][c + 1] + h.z * w[1][c + 2] + h.w * w[1][c + 3];
    float pv = h.x * w[2][c] + h.y * w[2][c + 1] + h.z * w[2][c + 2] + h.w * w[2][c + 3];
    float ps = h.x * w[3][c] + h.y * w[3][c + 1] + h.z * w[3][c + 2] + h.w * w[3][c + 3];
#pragma unroll
    for (int o = 16; o; o >>= 1) {
        pk += __shfl_xor_sync(0xFFFFFFFFu, pk, o);
        pq += __shfl_xor_sync(0xFFFFFFFFu, pq, o);
        pv += __shfl_xor_sync(0xFFFFFFFFu, pv, o);
        ps += __shfl_xor_sync(0xFFFFFFFFu, ps, o);
    }
    if (lane == 0) g_P3[node] = make_float4(pk, pq, pv, ps + b[0]);
}

// ---------------- layer 3 aggregation: thread per node ----------------
__global__ void agg3_k(float* __restrict__ out, int n) {
    int i = blockIdx.x * blockDim.x + threadIdx.x;
    if (i >= n) return;
    float4 p = g_P3[i];
    float acc = p.w;
    int beg = g_rowoff[i], end = g_rowoff[i + 1];
    for (int e = beg; e < end; e++) {
        float4 ps = __ldg(&g_P3[g_srcsorted[e]]);
        acc = fmaf(fsig(p.x + ps.y), ps.z, acc);
    }
    out[i] = acc;
}

// ---------------- launch ----------------
extern "C" void kernel_launch(void* const* d_in, const int* in_sizes, int n_in,
                              void* d_out, int out_size) {
    const float* x  = (const float*)d_in[0];
    const int*   ei = (const int*)d_in[1];
    const float* Wk1 = (const float*)d_in[2];
    const float* Wq1 = (const float*)d_in[3];
    const float* Wv1 = (const float*)d_in[4];
    const float* Ws1 = (const float*)d_in[5];
    const float* b1  = (const float*)d_in[6];
    const float* Wk2 = (const float*)d_in[7];
    const float* Wq2 = (const float*)d_in[8];
    const float* Wv2 = (const float*)d_in[9];
    const float* Ws2 = (const float*)d_in[10];
    const float* b2  = (const float*)d_in[11];
    const float* Wk3 = (const float*)d_in[12];
    const float* Wq3 = (const float*)d_in[13];
    const float* Wv3 = (const float*)d_in[14];
    const float* Ws3 = (const float*)d_in[15];
    const float* b3  = (const float*)d_in[16];

    int N = in_sizes[0] / DD;     // 100000
    int E = in_sizes[1] / 2;      // 1600000
    const int* src = ei;
    const int* dst = ei + E;

    void *pH1, *pH2;
    cudaGetSymbolAddress(&pH1, g_H1);
    cudaGetSymbolAddress(&pH2, g_H2);
    float* H1 = (float*)pH1;
    float* H2 = (float*)pH2;

    const int SMEMSZ = 4 * 128 * TSTRIDE * 2;   // 139264
    cudaFuncSetAttribute(mma_gemm, cudaFuncAttributeMaxDynamicSharedMemorySize, SMEMSZ);

    // CSR by dst
    zero_counts_k<<<(N + 255) / 256, 256>>>(N);
    hist_k<<<(E + 255) / 256, 256>>>(dst, E);
    scan_k<<<1, 1024>>>(N);
    scatter_k<<<(E + 255) / 256, 256>>>(src, dst, E);

    int cvtb = (NP * DD / 8 + 255) / 256;
    int ab = (N + 7) / 8;
    dim3 gg(NBLK, 4);

    // layer 1
    cvt_k<<<cvtb, 256>>>(x, N * DD);
    packw_k<<<256, 256>>>(Wk1, Wq1, Wv1, Ws1);
    mma_gemm<<<gg, 256, SMEMSZ>>>(b1);
    agg128<<<ab, 256>>>(H1, 1, N);

    // layer 2
    cvt_k<<<cvtb, 256>>>(H1, N * DD);
    packw_k<<<256, 256>>>(Wk2, Wq2, Wv2, Ws2);
    mma_gemm<<<gg, 256, SMEMSZ>>>(b2);
    agg128<<<ab, 256>>>(H2, 1, N);

    // layer 3
    proj3_k<<<ab, 256>>>(Wk3, Wq3, Wv3, Ws3, b3, N);
    agg3_k<<<(N + 255) / 256, 256>>>((float*)d_out, N);
}

// round 7
// speedup vs baseline: 1.6947x; 1.0563x over previous
#include <cuda_runtime.h>
#include <cuda_bf16.h>
#include <cstdint>

#define NN 100000
#define DD 128
#define EMAX 1600000
#define NP 100096          // 782 * 128 (padded rows)
#define NBLK 782
#define TSTRIDE 136        // padded bf16 row stride: conflict-free ldmatrix

// ---------------- scratch (device globals: no allocation allowed) ----------------
__device__ float g_K[NP * DD];
__device__ float g_QV[NP * 2 * DD];   // per node: q[0..127], v[128..255]
__device__ float g_S[NP * DD];
__device__ float g_H2[NP * DD];
__device__ __nv_bfloat16 g_Ahi[NP * DD];
__device__ __nv_bfloat16 g_Alo[NP * DD];
__device__ __nv_bfloat16 g_Whi[512 * 128];   // [n_out][k], n_out = concat(k,q,v,s)
__device__ __nv_bfloat16 g_Wlo[512 * 128];
__device__ float4 g_P3[NP];
__device__ int g_counts[NN];
__device__ int g_rowoff[NN + 1];
__device__ int g_cursor[NN];
__device__ int g_srcsorted[EMAX];

// ---------------- helpers ----------------
__device__ __forceinline__ uint32_t smem_u32(const void* p) {
    uint32_t a;
    asm("{ .reg .u64 t; cvta.to.shared.u64 t, %1; cvt.u32.u64 %0, t; }" : "=r"(a) : "l"(p));
    return a;
}

#define LDSM_X4(r0, r1, r2, r3, addr)                                          \
    asm volatile("ldmatrix.sync.aligned.m8n8.x4.shared.b16 {%0,%1,%2,%3}, [%4];" \
                 : "=r"(r0), "=r"(r1), "=r"(r2), "=r"(r3) : "r"(addr))

#define MMA16816(d, a, b0, b1)                                                 \
    asm volatile("mma.sync.aligned.m16n8k16.row.col.f32.bf16.bf16.f32 "        \
                 "{%0,%1,%2,%3}, {%4,%5,%6,%7}, {%8,%9}, {%0,%1,%2,%3};"       \
                 : "+f"((d)[0]), "+f"((d)[1]), "+f"((d)[2]), "+f"((d)[3])      \
                 : "r"((a)[0]), "r"((a)[1]), "r"((a)[2]), "r"((a)[3]),         \
                   "r"(b0), "r"(b1))

// ---------------- MUFU-based sigmoid ----------------
__device__ __forceinline__ float fsig(float t) {
    return __fdividef(1.0f, 1.0f + __expf(-t));
}

// safe bf16 hi/lo split pack: two floats -> (hi_pair, lo_pair) uint32s
__device__ __forceinline__ void pack_hl(float a, float b, uint32_t& hp, uint32_t& lp) {
    __nv_bfloat16 ha = __float2bfloat16(a);
    __nv_bfloat16 hb = __float2bfloat16(b);
    __nv_bfloat16 la = __float2bfloat16(a - __bfloat162float(ha));
    __nv_bfloat16 lb = __float2bfloat16(b - __bfloat162float(hb));
    hp = (uint32_t)__bfloat16_as_ushort(ha) | ((uint32_t)__bfloat16_as_ushort(hb) << 16);
    lp = (uint32_t)__bfloat16_as_ushort(la) | ((uint32_t)__bfloat16_as_ushort(lb) << 16);
}

// ---------------- CSR build ----------------
__global__ void zero_counts_k(int n) {
    int i = blockIdx.x * blockDim.x + threadIdx.x;
    if (i < n) g_counts[i] = 0;
}
__global__ void hist_k(const int* __restrict__ dst, int e) {
    int i = blockIdx.x * blockDim.x + threadIdx.x;
    if (i < e) atomicAdd(&g_counts[dst[i]], 1);
}
__global__ void scan_k(int n) {
    __shared__ int sums[1024];
    int tid = threadIdx.x;
    int chunk = (n + 1023) >> 10;
    int b = tid * chunk, e = min(b + chunk, n);
    int s = 0;
    for (int i = b; i < e; i++) s += g_counts[i];
    sums[tid] = s;
    __syncthreads();
    for (int off = 1; off < 1024; off <<= 1) {
        int v = (tid >= off) ? sums[tid - off] : 0;
        __syncthreads();
        sums[tid] += v;
        __syncthreads();
    }
    int run = tid ? sums[tid - 1] : 0;
    for (int i = b; i < e; i++) {
        g_rowoff[i] = run;
        g_cursor[i] = run;
        run += g_counts[i];
    }
    if (tid == 1023) g_rowoff[n] = sums[1023];
}
__global__ void scatter_k(const int* __restrict__ src, const int* __restrict__ dst, int e) {
    int i = blockIdx.x * blockDim.x + threadIdx.x;
    if (i < e) {
        int p = atomicAdd(&g_cursor[dst[i]], 1);
        g_srcsorted[p] = src[i];
    }
}

// ---------------- bf16 split conversion (layer 1 input only) ----------------
__global__ void cvt_k(const float* __restrict__ x, int nreal) {
    int i = (blockIdx.x * blockDim.x + threadIdx.x) * 8;
    if (i >= NP * DD) return;
    __nv_bfloat16 h[8], l[8];
#pragma unroll
    for (int j = 0; j < 8; j++) {
        float v = (i + j < nreal) ? x[i + j] : 0.0f;
        h[j] = __float2bfloat16(v);
        l[j] = __float2bfloat16(v - __bfloat162float(h[j]));
    }
    *(uint4*)(g_Ahi + i) = *(uint4*)h;
    *(uint4*)(g_Alo + i) = *(uint4*)l;
}

__global__ void packw_k(const float* __restrict__ Wk, const float* __restrict__ Wq,
                        const float* __restrict__ Wv, const float* __restrict__ Ws) {
    int i = blockIdx.x * blockDim.x + threadIdx.x;   // 512*128
    if (i >= 512 * 128) return;
    int n = i >> 7, k = i & 127;
    const float* W = (n < 128) ? Wk : (n < 256) ? Wq : (n < 384) ? Wv : Ws;
    float v = W[k * 128 + (n & 127)];
    __nv_bfloat16 h = __float2bfloat16(v);
    g_Whi[i] = h;
    g_Wlo[i] = __float2bfloat16(v - __bfloat162float(h));
}

// ---------------- mma.sync bf16 split GEMM (R3-proven structure) ----------------
// CTA: 128 rows x 128 cols (of N=512 concat), K=128 resident in SMEM.
// 256 threads = 8 warps (4 m-blocks x 2 n-blocks); warp tile 32x64.
// acc = Ahi*Bhi + Alo*Bhi + Ahi*Blo  (fp32 accum; rel err ~2^-17)
__global__ void __launch_bounds__(256, 1) mma_gemm(const float* __restrict__ bias) {
    extern __shared__ __nv_bfloat16 sm[];
    __nv_bfloat16* Ah = sm;
    __nv_bfloat16* Al = sm + 128 * TSTRIDE;
    __nv_bfloat16* Bh = sm + 2 * 128 * TSTRIDE;
    __nv_bfloat16* Bl = sm + 3 * 128 * TSTRIDE;

    int tid = threadIdx.x;
    int row0 = blockIdx.x * 128;
    int col0 = blockIdx.y * 128;

    // cooperative load: each thread 8 x uint4 per tile
#pragma unroll
    for (int i = 0; i < 8; i++) {
        int c = tid + i * 256;
        int r = c >> 4, col = (c & 15) * 8;
        *(uint4*)(Ah + r * TSTRIDE + col) = *(const uint4*)(g_Ahi + (size_t)(row0 + r) * 128 + col);
        *(uint4*)(Al + r * TSTRIDE + col) = *(const uint4*)(g_Alo + (size_t)(row0 + r) * 128 + col);
        *(uint4*)(Bh + r * TSTRIDE + col) = *(const uint4*)(g_Whi + (size_t)(col0 + r) * 128 + col);
        *(uint4*)(Bl + r * TSTRIDE + col) = *(const uint4*)(g_Wlo + (size_t)(col0 + r) * 128 + col);
    }
    __syncthreads();

    int w = tid >> 5, lane = tid & 31;
    int m_base = (w & 3) * 32;
    int n_base = (w >> 2) * 64;

    float acc[2][8][4];
#pragma unroll
    for (int mi = 0; mi < 2; mi++)
#pragma unroll
        for (int ni = 0; ni < 8; ni++)
#pragma unroll
            for (int j = 0; j < 4; j++) acc[mi][ni][j] = 0.0f;

    // ldmatrix address patterns
    int a_row = lane & 15, a_colsel = (lane >> 4) * 8;          // A x4: m16 x k16
    int b_grp = lane >> 3;                                      // B x4: n16 x k16
    int b_row = (b_grp >> 1) * 8 + (lane & 7);
    int b_col = (b_grp & 1) * 8;

    uint32_t sAh = smem_u32(Ah), sAl = smem_u32(Al);
    uint32_t sBh = smem_u32(Bh), sBl = smem_u32(Bl);

#pragma unroll
    for (int ks = 0; ks < 8; ks++) {
        int k0 = ks * 16;
        uint32_t ah[2][4], al[2][4], bh[4][4], bl[4][4];
#pragma unroll
        for (int mi = 0; mi < 2; mi++) {
            uint32_t off = (uint32_t)((m_base + mi * 16 + a_row) * TSTRIDE + k0 + a_colsel) * 2;
            LDSM_X4(ah[mi][0], ah[mi][1], ah[mi][2], ah[mi][3], sAh + off);
            LDSM_X4(al[mi][0], al[mi][1], al[mi][2], al[mi][3], sAl + off);
        }
#pragma unroll
        for (int j = 0; j < 4; j++) {
            uint32_t off = (uint32_t)((n_base + j * 16 + b_row) * TSTRIDE + k0 + b_col) * 2;
            LDSM_X4(bh[j][0], bh[j][1], bh[j][2], bh[j][3], sBh + off);
            LDSM_X4(bl[j][0], bl[j][1], bl[j][2], bl[j][3], sBl + off);
        }
#pragma unroll
        for (int mi = 0; mi < 2; mi++)
#pragma unroll
            for (int ni = 0; ni < 8; ni++) {
                int j = ni >> 1, h = (ni & 1) * 2;
                MMA16816(acc[mi][ni], ah[mi], bh[j][h], bh[j][h + 1]);
                MMA16816(acc[mi][ni], al[mi], bh[j][h], bh[j][h + 1]);
                MMA16816(acc[mi][ni], ah[mi], bl[j][h], bl[j][h + 1]);
            }
    }

    // epilogue: scatter into K / QV / S
    int by = blockIdx.y;
    float* base;
    int stride, coff;
    if (by == 0)      { base = g_K;  stride = 128; coff = 0; }
    else if (by == 1) { base = g_QV; stride = 256; coff = 0; }
    else if (by == 2) { base = g_QV; stride = 256; coff = 128; }
    else              { base = g_S;  stride = 128; coff = 0; }

    int r_in = lane >> 2;
    int c_in = (lane & 3) * 2;
#pragma unroll
    for (int mi = 0; mi < 2; mi++)
#pragma unroll
        for (int half = 0; half < 2; half++)
#pragma unroll
            for (int ni = 0; ni < 8; ni++) {
                int r = row0 + m_base + mi * 16 + half * 8 + r_in;
                int c = n_base + ni * 8 + c_in;
                float2 v = make_float2(acc[mi][ni][half * 2], acc[mi][ni][half * 2 + 1]);
                if (by == 3) {
                    v.x += __ldg(&bias[c]);
                    v.y += __ldg(&bias[c + 1]);
                }
                *(float2*)(base + (size_t)r * stride + coff + c) = v;
            }
}

// ---------------- gated aggregation, D=128: warp per node ----------------
// ReLU is ALWAYS applied (reference: relu(conv1), relu(conv2)).
// MODE 0: write result as bf16 hi/lo split (feeds next layer's GEMM)
// MODE 1: write fp32 (feeds proj3)
template <int MODE>
__global__ void __launch_bounds__(256) agg128(float* __restrict__ outf, int n) {
    int node = blockIdx.x * 8 + (threadIdx.x >> 5);
    if (node >= n) return;
    int lane = threadIdx.x & 31;
    int beg = g_rowoff[node], end = g_rowoff[node + 1];
    const float4* kp = (const float4*)(g_K + (size_t)node * DD);
    float4 k = kp[lane];
    float4 acc = make_float4(0.f, 0.f, 0.f, 0.f);
    const float4* QV4 = (const float4*)g_QV;
#pragma unroll 2
    for (int e = beg; e < end; e++) {
        int s = g_srcsorted[e];
        const float4* qv = QV4 + (size_t)s * 64;
        float4 q = __ldg(&qv[lane]);
        float4 v = __ldg(&qv[32 + lane]);
        acc.x = fmaf(fsig(k.x + q.x), v.x, acc.x);
        acc.y = fmaf(fsig(k.y + q.y), v.y, acc.y);
        acc.z = fmaf(fsig(k.z + q.z), v.z, acc.z);
        acc.w = fmaf(fsig(k.w + q.w), v.w, acc.w);
    }
    const float4* sp = (const float4*)(g_S + (size_t)node * DD);
    float4 sv = sp[lane];
    float4 r = make_float4(fmaxf(acc.x + sv.x, 0.f), fmaxf(acc.y + sv.y, 0.f),
                           fmaxf(acc.z + sv.z, 0.f), fmaxf(acc.w + sv.w, 0.f));
    if (MODE == 0) {
        uint32_t h0, h1, l0, l1;
        pack_hl(r.x, r.y, h0, l0);
        pack_hl(r.z, r.w, h1, l1);
        size_t off = (size_t)node * DD + lane * 4;
        *(uint2*)(g_Ahi + off) = make_uint2(h0, h1);
        *(uint2*)(g_Alo + off) = make_uint2(l0, l1);
    } else {
        ((float4*)(outf + (size_t)node * DD))[lane] = r;
    }
}

// ---------------- layer 3 projection: 4 dot products per node (Dout=1) ----------------
__global__ void __launch_bounds__(256) proj3_k(
    const float* __restrict__ Wk, const float* __restrict__ Wq,
    const float* __restrict__ Wv, const float* __restrict__ Ws,
    const float* __restrict__ b, int n)
{
    __shared__ float w[4][128];
    int tid = threadIdx.x;
    if (tid < 128) { w[0][tid] = Wk[tid]; w[1][tid] = Wq[tid]; }
    else { int t = tid - 128; w[2][t] = Wv[t]; w[3][t] = Ws[t]; }
    __syncthreads();
    int node = blockIdx.x * 8 + (tid >> 5);
    if (node >= n) return;
    int lane = tid & 31;
    float4 h = ((const float4*)(g_H2 + (size_t)node * DD))[lane];
    int c = lane * 4;
    float pk = h.x * w[0][c] + h.y * w[0][c + 1] + h.z * w[0][c + 2] + h.w * w[0][c + 3];
    float pq = h.x * w[1][c] + h.y * w[1][c + 1] + h.z * w[1][c + 2] + h.w * w[1][c + 3];
    float pv = h.x * w[2][c] + h.y * w[2][c + 1] + h.z * w[2][c + 2] + h.w * w[2][c + 3];
    float ps = h.x * w[3][c] + h.y * w[3][c + 1] + h.z * w[3][c + 2] + h.w * w[3][c + 3];
#pragma unroll
    for (int o = 16; o; o >>= 1) {
        pk += __shfl_xor_sync(0xFFFFFFFFu, pk, o);
        pq += __shfl_xor_sync(0xFFFFFFFFu, pq, o);
        pv += __shfl_xor_sync(0xFFFFFFFFu, pv, o);
        ps += __shfl_xor_sync(0xFFFFFFFFu, ps, o);
    }
    if (lane == 0) g_P3[node] = make_float4(pk, pq, pv, ps + b[0]);
}

// ---------------- layer 3 aggregation: thread per node ----------------
__global__ void agg3_k(float* __restrict__ out, int n) {
    int i = blockIdx.x * blockDim.x + threadIdx.x;
    if (i >= n) return;
    float4 p = g_P3[i];
    float acc = p.w;
    int beg = g_rowoff[i], end = g_rowoff[i + 1];
    for (int e = beg; e < end; e++) {
        float4 ps = __ldg(&g_P3[g_srcsorted[e]]);
        acc = fmaf(fsig(p.x + ps.y), ps.z, acc);
    }
    out[i] = acc;
}

// ---------------- launch ----------------
extern "C" void kernel_launch(void* const* d_in, const int* in_sizes, int n_in,
                              void* d_out, int out_size) {
    const float* x  = (const float*)d_in[0];
    const int*   ei = (const int*)d_in[1];
    const float* Wk1 = (const float*)d_in[2];
    const float* Wq1 = (const float*)d_in[3];
    const float* Wv1 = (const float*)d_in[4];
    const float* Ws1 = (const float*)d_in[5];
    const float* b1  = (const float*)d_in[6];
    const float* Wk2 = (const float*)d_in[7];
    const float* Wq2 = (const float*)d_in[8];
    const float* Wv2 = (const float*)d_in[9];
    const float* Ws2 = (const float*)d_in[10];
    const float* b2  = (const float*)d_in[11];
    const float* Wk3 = (const float*)d_in[12];
    const float* Wq3 = (const float*)d_in[13];
    const float* Wv3 = (const float*)d_in[14];
    const float* Ws3 = (const float*)d_in[15];
    const float* b3  = (const float*)d_in[16];

    int N = in_sizes[0] / DD;     // 100000
    int E = in_sizes[1] / 2;      // 1600000
    const int* src = ei;
    const int* dst = ei + E;

    void* pH2;
    cudaGetSymbolAddress(&pH2, g_H2);
    float* H2 = (float*)pH2;

    const int SMEMSZ = 4 * 128 * TSTRIDE * 2;   // 139264
    cudaFuncSetAttribute(mma_gemm, cudaFuncAttributeMaxDynamicSharedMemorySize, SMEMSZ);

    // CSR by dst
    zero_counts_k<<<(N + 255) / 256, 256>>>(N);
    hist_k<<<(E + 255) / 256, 256>>>(dst, E);
    scan_k<<<1, 1024>>>(N);
    scatter_k<<<(E + 255) / 256, 256>>>(src, dst, E);

    int cvtb = (NP * DD / 8 + 255) / 256;
    int ab = (N + 7) / 8;
    dim3 gg(NBLK, 4);

    // layer 1
    cvt_k<<<cvtb, 256>>>(x, N * DD);
    packw_k<<<256, 256>>>(Wk1, Wq1, Wv1, Ws1);
    mma_gemm<<<gg, 256, SMEMSZ>>>(b1);
    agg128<0><<<ab, 256>>>(nullptr, N);          // ReLU + bf16 split write (feeds GEMM2)

    // layer 2
    packw_k<<<256, 256>>>(Wk2, Wq2, Wv2, Ws2);
    mma_gemm<<<gg, 256, SMEMSZ>>>(b2);
    agg128<1><<<ab, 256>>>(H2, N);               // ReLU + fp32 write (feeds proj3)

    // layer 3
    proj3_k<<<ab, 256>>>(Wk3, Wq3, Wv3, Ws3, b3, N);
    agg3_k<<<(N + 255) / 256, 256>>>((float*)d_out, N);
}

// round 8
// speedup vs baseline: 1.7145x; 1.0117x over previous
#include <cuda_runtime.h>
#include <cuda_bf16.h>
#include <cstdint>

#define NN 100000
#define DD 128
#define EMAX 1600000
#define NP 100096          // 782 * 128 (padded rows)
#define NBLK 782
#define TSTRIDE 136        // padded bf16 row stride: conflict-free ldmatrix

// ---------------- scratch (device globals: no allocation allowed) ----------------
__device__ float g_K[NP * DD];
__device__ float g_QV[NP * 2 * DD];   // per node: q[0..127], v[128..255]
__device__ float g_S[NP * DD];
__device__ float g_H2[NP * DD];
__device__ __nv_bfloat16 g_Ahi[NP * DD];   // layer-2 GEMM input (written by agg128<0>; pad rows stay 0)
__device__ __nv_bfloat16 g_Alo[NP * DD];
__device__ __nv_bfloat16 g_Whi[512 * 128]; // [n_out][k], n_out = concat(k,q,v,s)
__device__ __nv_bfloat16 g_Wlo[512 * 128];
__device__ float4 g_P3[NP];
__device__ int g_counts[NN];
__device__ int g_rowoff[NN + 1];
__device__ int g_cursor[NN];
__device__ int g_srcsorted[EMAX];

// ---------------- helpers ----------------
__device__ __forceinline__ uint32_t smem_u32(const void* p) {
    uint32_t a;
    asm("{ .reg .u64 t; cvta.to.shared.u64 t, %1; cvt.u32.u64 %0, t; }" : "=r"(a) : "l"(p));
    return a;
}

#define LDSM_X4(r0, r1, r2, r3, addr)                                          \
    asm volatile("ldmatrix.sync.aligned.m8n8.x4.shared.b16 {%0,%1,%2,%3}, [%4];" \
                 : "=r"(r0), "=r"(r1), "=r"(r2), "=r"(r3) : "r"(addr))

#define MMA16816(d, a, b0, b1)                                                 \
    asm volatile("mma.sync.aligned.m16n8k16.row.col.f32.bf16.bf16.f32 "        \
                 "{%0,%1,%2,%3}, {%4,%5,%6,%7}, {%8,%9}, {%0,%1,%2,%3};"       \
                 : "+f"((d)[0]), "+f"((d)[1]), "+f"((d)[2]), "+f"((d)[3])      \
                 : "r"((a)[0]), "r"((a)[1]), "r"((a)[2]), "r"((a)[3]),         \
                   "r"(b0), "r"(b1))

// ---------------- MUFU-based sigmoid ----------------
__device__ __forceinline__ float fsig(float t) {
    return __fdividef(1.0f, 1.0f + __expf(-t));
}

// safe bf16 hi/lo split pack: two floats -> (hi_pair, lo_pair) uint32s
__device__ __forceinline__ void pack_hl(float a, float b, uint32_t& hp, uint32_t& lp) {
    __nv_bfloat16 ha = __float2bfloat16(a);
    __nv_bfloat16 hb = __float2bfloat16(b);
    __nv_bfloat16 la = __float2bfloat16(a - __bfloat162float(ha));
    __nv_bfloat16 lb = __float2bfloat16(b - __bfloat162float(hb));
    hp = (uint32_t)__bfloat16_as_ushort(ha) | ((uint32_t)__bfloat16_as_ushort(hb) << 16);
    lp = (uint32_t)__bfloat16_as_ushort(la) | ((uint32_t)__bfloat16_as_ushort(lb) << 16);
}

// ---------------- CSR build ----------------
__global__ void zero_counts_k(int n) {
    int i = blockIdx.x * blockDim.x + threadIdx.x;
    if (i < n) g_counts[i] = 0;
}
__global__ void hist_k(const int* __restrict__ dst, int e) {
    int i = blockIdx.x * blockDim.x + threadIdx.x;
    if (i < e) atomicAdd(&g_counts[dst[i]], 1);
}
__global__ void scan_k(int n) {
    __shared__ int sums[1024];
    int tid = threadIdx.x;
    int chunk = (n + 1023) >> 10;
    int b = tid * chunk, e = min(b + chunk, n);
    int s = 0;
    for (int i = b; i < e; i++) s += g_counts[i];
    sums[tid] = s;
    __syncthreads();
    for (int off = 1; off < 1024; off <<= 1) {
        int v = (tid >= off) ? sums[tid - off] : 0;
        __syncthreads();
        sums[tid] += v;
        __syncthreads();
    }
    int run = tid ? sums[tid - 1] : 0;
    for (int i = b; i < e; i++) {
        g_rowoff[i] = run;
        g_cursor[i] = run;
        run += g_counts[i];
    }
    if (tid == 1023) g_rowoff[n] = sums[1023];
}
__global__ void scatter_k(const int* __restrict__ src, const int* __restrict__ dst, int e) {
    int i = blockIdx.x * blockDim.x + threadIdx.x;
    if (i < e) {
        int p = atomicAdd(&g_cursor[dst[i]], 1);
        g_srcsorted[p] = src[i];
    }
}

// ---------------- weight packing ----------------
__global__ void packw_k(const float* __restrict__ Wk, const float* __restrict__ Wq,
                        const float* __restrict__ Wv, const float* __restrict__ Ws) {
    int i = blockIdx.x * blockDim.x + threadIdx.x;   // 512*128
    if (i >= 512 * 128) return;
    int n = i >> 7, k = i & 127;
    const float* W = (n < 128) ? Wk : (n < 256) ? Wq : (n < 384) ? Wv : Ws;
    float v = W[k * 128 + (n & 127)];
    __nv_bfloat16 h = __float2bfloat16(v);
    g_Whi[i] = h;
    g_Wlo[i] = __float2bfloat16(v - __bfloat162float(h));
}

// ---------------- mma.sync bf16 split GEMM ----------------
// CTA: 128 rows x 128 cols (of N=512 concat), K=128 resident in SMEM.
// 256 threads = 8 warps (4 m-blocks x 2 n-blocks); warp tile 32x64.
// acc = Ahi*Bhi + Alo*Bhi + Ahi*Blo  (fp32 accum; rel err ~2^-17)
// SRC=0: A from g_Ahi/g_Alo bf16 arrays. SRC=1: A from fp32 xin, split on the fly.
template <int SRC>
__global__ void __launch_bounds__(256, 1) mma_gemm(
    const float* __restrict__ bias, const float* __restrict__ xin, int nrows)
{
    extern __shared__ __nv_bfloat16 sm[];
    __nv_bfloat16* Ah = sm;
    __nv_bfloat16* Al = sm + 128 * TSTRIDE;
    __nv_bfloat16* Bh = sm + 2 * 128 * TSTRIDE;
    __nv_bfloat16* Bl = sm + 3 * 128 * TSTRIDE;

    int tid = threadIdx.x;
    int row0 = blockIdx.x * 128;
    int col0 = blockIdx.y * 128;

    if (SRC == 0) {
        // cooperative load: each thread 8 x uint4 per tile (A + B, all bf16)
#pragma unroll
        for (int i = 0; i < 8; i++) {
            int c = tid + i * 256;
            int r = c >> 4, col = (c & 15) * 8;
            *(uint4*)(Ah + r * TSTRIDE + col) = *(const uint4*)(g_Ahi + (size_t)(row0 + r) * 128 + col);
            *(uint4*)(Al + r * TSTRIDE + col) = *(const uint4*)(g_Alo + (size_t)(row0 + r) * 128 + col);
            *(uint4*)(Bh + r * TSTRIDE + col) = *(const uint4*)(g_Whi + (size_t)(col0 + r) * 128 + col);
            *(uint4*)(Bl + r * TSTRIDE + col) = *(const uint4*)(g_Wlo + (size_t)(col0 + r) * 128 + col);
        }
    } else {
        // B tiles bf16
#pragma unroll
        for (int i = 0; i < 8; i++) {
            int c = tid + i * 256;
            int r = c >> 4, col = (c & 15) * 8;
            *(uint4*)(Bh + r * TSTRIDE + col) = *(const uint4*)(g_Whi + (size_t)(col0 + r) * 128 + col);
            *(uint4*)(Bl + r * TSTRIDE + col) = *(const uint4*)(g_Wlo + (size_t)(col0 + r) * 128 + col);
        }
        // A tile fp32 -> bf16 hi/lo split on the fly (row-bounds guarded)
#pragma unroll
        for (int i = 0; i < 16; i++) {
            int c = tid + i * 256;
            int r = c >> 5, col = (c & 31) * 4;
            float4 v = make_float4(0.f, 0.f, 0.f, 0.f);
            if (row0 + r < nrows)
                v = *(const float4*)(xin + (size_t)(row0 + r) * 128 + col);
            uint32_t h0, l0, h1, l1;
            pack_hl(v.x, v.y, h0, l0);
            pack_hl(v.z, v.w, h1, l1);
            *(uint2*)(Ah + r * TSTRIDE + col) = make_uint2(h0, h1);
            *(uint2*)(Al + r * TSTRIDE + col) = make_uint2(l0, l1);
        }
    }
    __syncthreads();

    int w = tid >> 5, lane = tid & 31;
    int m_base = (w & 3) * 32;
    int n_base = (w >> 2) * 64;

    float acc[2][8][4];
#pragma unroll
    for (int mi = 0; mi < 2; mi++)
#pragma unroll
        for (int ni = 0; ni < 8; ni++)
#pragma unroll
            for (int j = 0; j < 4; j++) acc[mi][ni][j] = 0.0f;

    // ldmatrix address patterns
    int a_row = lane & 15, a_colsel = (lane >> 4) * 8;          // A x4: m16 x k16
    int b_grp = lane >> 3;                                      // B x4: n16 x k16
    int b_row = (b_grp >> 1) * 8 + (lane & 7);
    int b_col = (b_grp & 1) * 8;

    uint32_t sAh = smem_u32(Ah), sAl = smem_u32(Al);
    uint32_t sBh = smem_u32(Bh), sBl = smem_u32(Bl);

#pragma unroll
    for (int ks = 0; ks < 8; ks++) {
        int k0 = ks * 16;
        uint32_t ah[2][4], al[2][4], bh[4][4], bl[4][4];
#pragma unroll
        for (int mi = 0; mi < 2; mi++) {
            uint32_t off = (uint32_t)((m_base + mi * 16 + a_row) * TSTRIDE + k0 + a_colsel) * 2;
            LDSM_X4(ah[mi][0], ah[mi][1], ah[mi][2], ah[mi][3], sAh + off);
            LDSM_X4(al[mi][0], al[mi][1], al[mi][2], al[mi][3], sAl + off);
        }
#pragma unroll
        for (int j = 0; j < 4; j++) {
            uint32_t off = (uint32_t)((n_base + j * 16 + b_row) * TSTRIDE + k0 + b_col) * 2;
            LDSM_X4(bh[j][0], bh[j][1], bh[j][2], bh[j][3], sBh + off);
            LDSM_X4(bl[j][0], bl[j][1], bl[j][2], bl[j][3], sBl + off);
        }
#pragma unroll
        for (int mi = 0; mi < 2; mi++)
#pragma unroll
            for (int ni = 0; ni < 8; ni++) {
                int j = ni >> 1, h = (ni & 1) * 2;
                MMA16816(acc[mi][ni], ah[mi], bh[j][h], bh[j][h + 1]);
                MMA16816(acc[mi][ni], al[mi], bh[j][h], bh[j][h + 1]);
                MMA16816(acc[mi][ni], ah[mi], bl[j][h], bl[j][h + 1]);
            }
    }

    // epilogue: scatter into K / QV / S
    int by = blockIdx.y;
    float* base;
    int stride, coff;
    if (by == 0)      { base = g_K;  stride = 128; coff = 0; }
    else if (by == 1) { base = g_QV; stride = 256; coff = 0; }
    else if (by == 2) { base = g_QV; stride = 256; coff = 128; }
    else              { base = g_S;  stride = 128; coff = 0; }

    int r_in = lane >> 2;
    int c_in = (lane & 3) * 2;
#pragma unroll
    for (int mi = 0; mi < 2; mi++)
#pragma unroll
        for (int half = 0; half < 2; half++)
#pragma unroll
            for (int ni = 0; ni < 8; ni++) {
                int r = row0 + m_base + mi * 16 + half * 8 + r_in;
                int c = n_base + ni * 8 + c_in;
                float2 v = make_float2(acc[mi][ni][half * 2], acc[mi][ni][half * 2 + 1]);
                if (by == 3) {
                    v.x += __ldg(&bias[c]);
                    v.y += __ldg(&bias[c + 1]);
                }
                *(float2*)(base + (size_t)r * stride + coff + c) = v;
            }
}

// ---------------- gated aggregation, D=128: warp per node ----------------
// ReLU is ALWAYS applied (reference: relu(conv1), relu(conv2)).
// MODE 0: write result as bf16 hi/lo split (feeds next layer's GEMM)
// MODE 1: write fp32 (feeds proj3)
template <int MODE>
__global__ void __launch_bounds__(256) agg128(float* __restrict__ outf, int n) {
    int node = blockIdx.x * 8 + (threadIdx.x >> 5);
    if (node >= n) return;
    int lane = threadIdx.x & 31;
    int beg = g_rowoff[node], end = g_rowoff[node + 1];
    const float4* kp = (const float4*)(g_K + (size_t)node * DD);
    float4 k = kp[lane];
    float4 acc = make_float4(0.f, 0.f, 0.f, 0.f);
    const float4* QV4 = (const float4*)g_QV;
#pragma unroll 2
    for (int e = beg; e < end; e++) {
        int s = g_srcsorted[e];
        const float4* qv = QV4 + (size_t)s * 64;
        float4 q = __ldg(&qv[lane]);
        float4 v = __ldg(&qv[32 + lane]);
        acc.x = fmaf(fsig(k.x + q.x), v.x, acc.x);
        acc.y = fmaf(fsig(k.y + q.y), v.y, acc.y);
        acc.z = fmaf(fsig(k.z + q.z), v.z, acc.z);
        acc.w = fmaf(fsig(k.w + q.w), v.w, acc.w);
    }
    const float4* sp = (const float4*)(g_S + (size_t)node * DD);
    float4 sv = sp[lane];
    float4 r = make_float4(fmaxf(acc.x + sv.x, 0.f), fmaxf(acc.y + sv.y, 0.f),
                           fmaxf(acc.z + sv.z, 0.f), fmaxf(acc.w + sv.w, 0.f));
    if (MODE == 0) {
        uint32_t h0, h1, l0, l1;
        pack_hl(r.x, r.y, h0, l0);
        pack_hl(r.z, r.w, h1, l1);
        size_t off = (size_t)node * DD + lane * 4;
        *(uint2*)(g_Ahi + off) = make_uint2(h0, h1);
        *(uint2*)(g_Alo + off) = make_uint2(l0, l1);
    } else {
        ((float4*)(outf + (size_t)node * DD))[lane] = r;
    }
}

// ---------------- layer 3 projection: 4 dot products per node (Dout=1) ----------------
__global__ void __launch_bounds__(256) proj3_k(
    const float* __restrict__ Wk, const float* __restrict__ Wq,
    const float* __restrict__ Wv, const float* __restrict__ Ws,
    const float* __restrict__ b, int n)
{
    __shared__ float w[4][128];
    int tid = threadIdx.x;
    if (tid < 128) { w[0][tid] = Wk[tid]; w[1][tid] = Wq[tid]; }
    else { int t = tid - 128; w[2][t] = Wv[t]; w[3][t] = Ws[t]; }
    __syncthreads();
    int node = blockIdx.x * 8 + (tid >> 5);
    if (node >= n) return;
    int lane = tid & 31;
    float4 h = ((const float4*)(g_H2 + (size_t)node * DD))[lane];
    int c = lane * 4;
    float pk = h.x * w[0][c] + h.y * w[0][c + 1] + h.z * w[0][c + 2] + h.w * w[0][c + 3];
    float pq = h.x * w[1][c] + h.y * w[1][c + 1] + h.z * w[1][c + 2] + h.w * w[1][c + 3];
    float pv = h.x * w[2][c] + h.y * w[2][c + 1] + h.z * w[2][c + 2] + h.w * w[2][c + 3];
    float ps = h.x * w[3][c] + h.y * w[3][c + 1] + h.z * w[3][c + 2] + h.w * w[3][c + 3];
#pragma unroll
    for (int o = 16; o; o >>= 1) {
        pk += __shfl_xor_sync(0xFFFFFFFFu, pk, o);
        pq += __shfl_xor_sync(0xFFFFFFFFu, pq, o);
        pv += __shfl_xor_sync(0xFFFFFFFFu, pv, o);
        ps += __shfl_xor_sync(0xFFFFFFFFu, ps, o);
    }
    if (lane == 0) g_P3[node] = make_float4(pk, pq, pv, ps + b[0]);
}

// ---------------- layer 3 aggregation: thread per node ----------------
__global__ void agg3_k(float* __restrict__ out, int n) {
    int i = blockIdx.x * blockDim.x + threadIdx.x;
    if (i >= n) return;
    float4 p = g_P3[i];
    float acc = p.w;
    int beg = g_rowoff[i], end = g_rowoff[i + 1];
    for (int e = beg; e < end; e++) {
        float4 ps = __ldg(&g_P3[g_srcsorted[e]]);
        acc = fmaf(fsig(p.x + ps.y), ps.z, acc);
    }
    out[i] = acc;
}

// ---------------- launch ----------------
extern "C" void kernel_launch(void* const* d_in, const int* in_sizes, int n_in,
                              void* d_out, int out_size) {
    const float* x  = (const float*)d_in[0];
    const int*   ei = (const int*)d_in[1];
    const float* Wk1 = (const float*)d_in[2];
    const float* Wq1 = (const float*)d_in[3];
    const float* Wv1 = (const float*)d_in[4];
    const float* Ws1 = (const float*)d_in[5];
    const float* b1  = (const float*)d_in[6];
    const float* Wk2 = (const float*)d_in[7];
    const float* Wq2 = (const float*)d_in[8];
    const float* Wv2 = (const float*)d_in[9];
    const float* Ws2 = (const float*)d_in[10];
    const float* b2  = (const float*)d_in[11];
    const float* Wk3 = (const float*)d_in[12];
    const float* Wq3 = (const float*)d_in[13];
    const float* Wv3 = (const float*)d_in[14];
    const float* Ws3 = (const float*)d_in[15];
    const float* b3  = (const float*)d_in[16];

    int N = in_sizes[0] / DD;     // 100000
    int E = in_sizes[1] / 2;      // 1600000
    const int* src = ei;
    const int* dst = ei + E;

    void* pH2;
    cudaGetSymbolAddress(&pH2, g_H2);
    float* H2 = (float*)pH2;

    const int SMEMSZ = 4 * 128 * TSTRIDE * 2;   // 139264
    cudaFuncSetAttribute(mma_gemm<0>, cudaFuncAttributeMaxDynamicSharedMemorySize, SMEMSZ);
    cudaFuncSetAttribute(mma_gemm<1>, cudaFuncAttributeMaxDynamicSharedMemorySize, SMEMSZ);

    int ab = (N + 7) / 8;
    dim3 gg(NBLK, 4);

    // fork: CSR build on side stream, concurrent with layer-1 GEMM pipeline
    cudaStream_t s1;
    cudaStreamCreateWithFlags(&s1, cudaStreamNonBlocking);
    cudaEvent_t ev0, evCSR;
    cudaEventCreateWithFlags(&ev0, cudaEventDisableTiming);
    cudaEventCreateWithFlags(&evCSR, cudaEventDisableTiming);

    cudaEventRecord(ev0, 0);
    cudaStreamWaitEvent(s1, ev0, 0);
    zero_counts_k<<<(N + 255) / 256, 256, 0, s1>>>(N);
    hist_k<<<(E + 255) / 256, 256, 0, s1>>>(dst, E);
    scan_k<<<1, 1024, 0, s1>>>(N);
    scatter_k<<<(E + 255) / 256, 256, 0, s1>>>(src, dst, E);
    cudaEventRecord(evCSR, s1);

    // layer 1 (main stream; fp32 x consumed directly by GEMM)
    packw_k<<<256, 256>>>(Wk1, Wq1, Wv1, Ws1);
    mma_gemm<1><<<gg, 256, SMEMSZ>>>(b1, x, N);

    // join CSR before first aggregation
    cudaStreamWaitEvent(0, evCSR, 0);
    agg128<0><<<ab, 256>>>(nullptr, N);          // ReLU + bf16 split write (feeds GEMM2)

    // layer 2
    packw_k<<<256, 256>>>(Wk2, Wq2, Wv2, Ws2);
    mma_gemm<0><<<gg, 256, SMEMSZ>>>(b2, nullptr, N);
    agg128<1><<<ab, 256>>>(H2, N);               // ReLU + fp32 write (feeds proj3)

    // layer 3
    proj3_k<<<ab, 256>>>(Wk3, Wq3, Wv3, Ws3, b3, N);
    agg3_k<<<(N + 255) / 256, 256>>>((float*)d_out, N);
}